// round 7
// baseline (speedup 1.0000x reference)
#include <cuda_runtime.h>
#include <cuda_bf16.h>

#define D        1024
#define NBLK     6
#define NV       7            // 6 blocks + partial
#define THREADS  256
#define REPS     1e-6f
#define INV_SCALE (1.0f/32.0f)   // 1/(sqrt(1024)*temperature)

__global__ __launch_bounds__(THREADS, 6)
void reskip_kernel(const float* __restrict__ blocks,
                   const float* __restrict__ partial,
                   const float* __restrict__ w_query,
                   const float* __restrict__ norm_w,
                   float* __restrict__ out,
                   int bt, long long blk_stride)
{
    __shared__ float s_qx[NV][8];
    __shared__ float s_xx[NV][8];
    __shared__ float s_sc[NV];          // per-vector scores
    __shared__ float s_coef[NV];        // c[0..5]=w1*exp_s[n], c[6]=partial_weight

    const int tok  = blockIdx.x;
    const int tid  = threadIdx.x;
    const int j    = tid * 4;               // this thread's 4 channels
    const long long base = (long long)tok * D + j;

    // effective query = w_query * norm_weight (fp32); hot in cache after wave 1
    float4 q4  = *(const float4*)(w_query + j);
    float4 nw4 = *(const float4*)(norm_w  + j);
    const float q0 = q4.x*nw4.x, q1 = q4.y*nw4.y, q2 = q4.z*nw4.z, q3 = q4.w*nw4.w;

    // ---- pass 1: stream the 7 vectors, compute q.x and x.x partials only.
    // Data is NOT staged: the epilogue re-loads it from L1D (per-CTA 28 KB,
    // 6 CTAs x 28 KB = 168 KB < 228 KB L1 => re-loads hit L1).
    float qx[NV], xx[NV];
    #pragma unroll
    for (int n = 0; n < NV; n++) {
        float4 v;
        if (n < NBLK)
            v = *(const float4*)(blocks + (long long)n * blk_stride + base);
        else
            v = *(const float4*)(partial + base);

        float a, s;
        a = q0 * v.x;         s = v.x * v.x;
        a = fmaf(q1, v.y, a); s = fmaf(v.y, v.y, s);
        a = fmaf(q2, v.z, a); s = fmaf(v.z, v.z, s);
        a = fmaf(q3, v.w, a); s = fmaf(v.w, v.w, s);
        qx[n] = a; xx[n] = s;
    }

    // Warp shuffle tree
    #pragma unroll
    for (int n = 0; n < NV; n++) {
        #pragma unroll
        for (int off = 16; off > 0; off >>= 1) {
            qx[n] += __shfl_xor_sync(0xffffffffu, qx[n], off);
            xx[n] += __shfl_xor_sync(0xffffffffu, xx[n], off);
        }
    }

    const int warp = tid >> 5, lane = tid & 31;
    if (lane == 0) {
        #pragma unroll
        for (int n = 0; n < NV; n++) { s_qx[n][warp] = qx[n]; s_xx[n][warp] = xx[n]; }
    }
    __syncthreads();

    // Lanes 0..6 of warp 0 finish the reductions in parallel (shortens MUFU tail)
    if (warp == 0 && lane < NV) {
        float a = 0.f, s = 0.f;
        #pragma unroll
        for (int w = 0; w < 8; w++) { a += s_qx[lane][w]; s += s_xx[lane][w]; }
        float inv = rsqrtf(s * (1.0f / (float)D) + REPS);
        s_sc[lane] = a * inv * INV_SCALE;
    }
    __syncwarp();

    if (tid == 0) {
        float sc[NV];
        #pragma unroll
        for (int n = 0; n < NV; n++) sc[n] = s_sc[n];

        // Phase-1 softmax over the 6 completed blocks
        float m1 = sc[0];
        #pragma unroll
        for (int n = 1; n < NBLK; n++) m1 = fmaxf(m1, sc[n]);
        float es[NBLK], lse = 0.f;
        #pragma unroll
        for (int n = 0; n < NBLK; n++) { es[n] = expf(sc[n] - m1); lse += es[n]; }
        float logl = logf(lse);
        float ent1 = 0.f;
        #pragma unroll
        for (int n = 0; n < NBLK; n++)
            ent1 -= (es[n] / lse) * ((sc[n] - m1) - logl);

        // Online-softmax merge with partial block
        float ps    = sc[6];
        float mm    = fmaxf(m1, ps);
        float c1    = expf(m1 - mm);
        float cp    = expf(ps - mm);
        float denom = c1 * lse + cp;
        float w1w   = c1 * lse / denom;     // phase1_weight
        float pw    = cp / denom;           // partial_weight

        #pragma unroll
        for (int n = 0; n < NBLK; n++) s_coef[n] = w1w * es[n];
        s_coef[6] = pw;

        float w1c = fmaxf(w1w, 1e-8f);
        float wpc = fmaxf(pw,  1e-8f);
        out[(long long)bt * D + tok] = w1c * ent1 - w1c * logf(w1c) - wpc * logf(wpc);
    }
    __syncthreads();

    float c[NV];
    #pragma unroll
    for (int n = 0; n < NV; n++) c[n] = s_coef[n];

    // ---- pass 2: re-load from global (L1 hits) and accumulate hidden.
    float o0, o1, o2, o3;
    {
        float4 v = *(const float4*)(partial + base);   // c[6] * partial first
        o0 = c[6] * v.x; o1 = c[6] * v.y; o2 = c[6] * v.z; o3 = c[6] * v.w;
    }
    #pragma unroll
    for (int n = 0; n < NBLK; n++) {
        float4 v = *(const float4*)(blocks + (long long)n * blk_stride + base);
        o0 = fmaf(c[n], v.x, o0);
        o1 = fmaf(c[n], v.y, o1);
        o2 = fmaf(c[n], v.z, o2);
        o3 = fmaf(c[n], v.w, o3);
    }
    *(float4*)(out + base) = make_float4(o0, o1, o2, o3);
}

extern "C" void kernel_launch(void* const* d_in, const int* in_sizes, int n_in,
                              void* d_out, int out_size)
{
    const float* blocks  = (const float*)d_in[0];   // [6, b, t, d]
    const float* partial = (const float*)d_in[1];   // [b, t, d]
    const float* wq      = (const float*)d_in[2];   // [d]
    const float* nw      = (const float*)d_in[3];   // [d]
    float* out           = (float*)d_out;           // [b*t*d hidden][b*t entropy]

    int bt = in_sizes[1] / D;                       // b*t tokens
    long long blk_stride = (long long)in_sizes[0] / NBLK;  // b*t*d

    reskip_kernel<<<bt, THREADS>>>(blocks, partial, wq, nw, out, bt, blk_stride);
}